// round 15
// baseline (speedup 1.0000x reference)
#include <cuda_runtime.h>
#include <cuda_fp16.h>
#include <cstdint>

#define NPTS 1000000
#define DX 300
#define DY 300
#define DZ 300
#define RNK  48
#define PSTR 64     // padded halves per plane cell (128 B, line-aligned)
#define VSTR 64     // vector cell: 64 half2 = 256 B ([0..23] lo pairs, [32..55] delta pairs)
#define NC   27

// fp16 planes (cell-major, 64-half padded rows)
__device__ __align__(16) __half g_xyH[DX * DY * PSTR];
__device__ __align__(16) __half g_xzH[DX * DZ * PSTR];
__device__ __align__(16) __half g_yzH[DY * DZ * PSTR];
// fp16 vectors, lo/delta pairs: cell i, rank-pair p:
//   [i*VSTR + p]      = (v[2p][i],           v[2p+1][i])
//   [i*VSTR + 32 + p] = (v[2p][i+1]-v[2p][i], v[2p+1][i+1]-v[2p+1][i])   (i+1 clamped)
__device__ __align__(16) __half2 g_xvP[DX * VSTR];
__device__ __align__(16) __half2 g_yvP[DY * VSTR];
__device__ __align__(16) __half2 g_zvP[DZ * VSTR];

typedef unsigned long long u64;

// ---------- smem layout (dynamic, bytes) ----------
#define ASTR 152
#define BSTR 40
#define OFF_A    0
#define OFF_B    (128 * ASTR * 2)                 // 38912
#define OFF_XYZ  (OFF_B + 144 * BSTR * 2)         // 50432
#define SMEM_TOT (OFF_XYZ + 128 * 3 * 4)          // 51968

__device__ __forceinline__ uint32_t smem_u32(const void* p) {
    uint32_t a;
    asm("{ .reg .u64 t; cvta.to.shared.u64 t, %1; cvt.u32.u64 %0, t; }" : "=r"(a) : "l"(p));
    return a;
}

// ---------- ldmatrix / mma.sync ----------
__device__ __forceinline__ void ldsm_x4(uint32_t addr, uint32_t r[4]) {
    asm volatile("ldmatrix.sync.aligned.m8n8.x4.shared.b16 {%0,%1,%2,%3}, [%4];"
                 : "=r"(r[0]), "=r"(r[1]), "=r"(r[2]), "=r"(r[3]) : "r"(addr));
}
__device__ __forceinline__ void ldsm_x4_t(uint32_t addr, uint32_t r[4]) {
    asm volatile("ldmatrix.sync.aligned.m8n8.x4.trans.shared.b16 {%0,%1,%2,%3}, [%4];"
                 : "=r"(r[0]), "=r"(r[1]), "=r"(r[2]), "=r"(r[3]) : "r"(addr));
}
__device__ __forceinline__ void mma16816(float d[4], const uint32_t a[4],
                                         uint32_t b0, uint32_t b1) {
    asm volatile(
        "mma.sync.aligned.m16n8k16.row.col.f32.f16.f16.f32 "
        "{%0,%1,%2,%3}, {%4,%5,%6,%7}, {%8,%9}, {%0,%1,%2,%3};"
        : "+f"(d[0]), "+f"(d[1]), "+f"(d[2]), "+f"(d[3])
        : "r"(a[0]), "r"(a[1]), "r"(a[2]), "r"(a[3]), "r"(b0), "r"(b1));
}

// ---------- merged transpose/convert ----------
__global__ void __launch_bounds__(128) transpose_all(
    const float* __restrict__ xy, const float* __restrict__ xz,
    const float* __restrict__ yz, const float* __restrict__ xv,
    const float* __restrict__ yv, const float* __restrict__ zv)
{
    __shared__ float tile[RNK][130];
    int b = blockIdx.x;
    int t = threadIdx.x;

    if (b < 2112) {
        const float* src;
        __half* dst;
        int base;
        const int cells = DX * DY;
        if (b < 704)       { src = xy; dst = g_xyH; base = b * 128; }
        else if (b < 1408) { src = xz; dst = g_xzH; base = (b - 704) * 128; }
        else               { src = yz; dst = g_yzH; base = (b - 1408) * 128; }

        int nc = cells - base;
        if (nc > 128) nc = 128;

        #pragma unroll
        for (int r = 0; r < RNK; r++) {
            if (t < nc) tile[r][t] = src[r * cells + base + t];
        }
        __syncthreads();
        __half2* dst2 = (__half2*)dst;
        for (int i = t; i < nc * 32; i += 128) {
            int cl = i >> 5;
            int p  = i & 31;
            float lo = (2 * p     < RNK) ? tile[2 * p][cl]     : 0.0f;
            float hi = (2 * p + 1 < RNK) ? tile[2 * p + 1][cl] : 0.0f;
            dst2[(u64)(base + cl) * 32 + p] = __floats2half2_rn(lo, hi);
        }
    } else {
        int vb = b - 2112;
        int vi = vb / 3;
        int base = (vb % 3) * 128;
        const int cells = DX;
        const float* src = (vi == 0) ? xv : ((vi == 1) ? yv : zv);
        __half2* dst = (vi == 0) ? g_xvP : ((vi == 1) ? g_yvP : g_zvP);

        int nc = cells - base;
        if (nc > 128) nc = 128;
        if (nc <= 0) return;

        #pragma unroll
        for (int r = 0; r < RNK; r++) {
            if (t < nc) tile[r][t] = src[r * cells + base + t];
        }
        // boundary column: cell base+nc (clamped)
        if (t < RNK) {
            int nxt = base + nc;
            if (nxt > cells - 1) nxt = cells - 1;
            tile[t][nc] = src[t * cells + nxt];
        }
        __syncthreads();
        for (int i = t; i < nc * 24; i += 128) {    // 24 rank-pairs per cell
            int cl = i / 24;
            int p  = i - cl * 24;
            float l0 = tile[2 * p][cl],     h0 = tile[2 * p][cl + 1];
            float l1 = tile[2 * p + 1][cl], h1 = tile[2 * p + 1][cl + 1];
            dst[(base + cl) * VSTR + p]      = __floats2half2_rn(l0, l1);
            dst[(base + cl) * VSTR + 32 + p] = __floats2half2_rn(h0 - l0, h1 - l1);
        }
    }
}

__device__ __forceinline__ void prep_coord(float g, int L, int& i0, int& i1, float& f)
{
    float t  = (g + 1.0f) * 0.5f;
    float ih = t * (float)(L - 1);
    int i = (int)floorf(ih);
    i = max(0, min(i, L - 1));
    i0 = i;
    i1 = min(i + 1, L - 1);
    f = ih - (float)i;
}

// plane corner gather for lane s: 16B (ranks 8s..8s+7) + 8B (ranks 32+4s..+3)
struct PC { uint4 a; uint2 b; };
__device__ __forceinline__ PC ldpc(const __half* cell, int s)
{
    PC r;
    r.a = *(const uint4*)((const char*)cell + s * 16);
    r.b = *(const uint2*)((const char*)cell + 64 + s * 8);
    return r;
}

// vector lo/delta gather for lane s
struct VP2 { uint4 lo_a; uint2 lo_b; uint4 dl_a; uint2 dl_b; };
__device__ __forceinline__ VP2 ldvp(const __half2* cell, int s)
{
    const char* p = (const char*)cell;
    VP2 r;
    r.lo_a = *(const uint4*)(p + 16 * s);          // rank-pairs 4s..4s+3
    r.lo_b = *(const uint2*)(p + 64 + 8 * s);      // rank-pairs 16+2s..+1
    r.dl_a = *(const uint4*)(p + 128 + 16 * s);
    r.dl_b = *(const uint2*)(p + 192 + 8 * s);
    return r;
}

__device__ __forceinline__ __half2 u2h2(unsigned u) { return *(__half2*)&u; }
__device__ __forceinline__ unsigned h22u(__half2 h) { return *(unsigned*)&h; }

// one segment, pure half2 datapath: bilinear (hfma2) * vec lerp (hfma2) -> A tile
__device__ __forceinline__ void fe_seg(
    const PC& c00, const PC& c01, const PC& c10, const PC& c11,
    const VP2& vp, int s,
    float fh, float fw, float fv, int seg, int prow, char* smA)
{
    __half2 W00 = __float2half2_rn((1.0f - fh) * (1.0f - fw));
    __half2 W01 = __float2half2_rn((1.0f - fh) * fw);
    __half2 W10 = __float2half2_rn(fh * (1.0f - fw));
    __half2 W11 = __float2half2_rn(fh * fw);
    __half2 FV  = __float2half2_rn(fv);

    const unsigned* a00 = (const unsigned*)&c00.a;
    const unsigned* a01 = (const unsigned*)&c01.a;
    const unsigned* a10 = (const unsigned*)&c10.a;
    const unsigned* a11 = (const unsigned*)&c11.a;
    const unsigned* la  = (const unsigned*)&vp.lo_a;
    const unsigned* da  = (const unsigned*)&vp.dl_a;

    unsigned feA[4];
    #pragma unroll
    for (int k = 0; k < 4; k++) {
        __half2 t = __hmul2(W00, u2h2(a00[k]));
        t = __hfma2(W01, u2h2(a01[k]), t);
        t = __hfma2(W10, u2h2(a10[k]), t);
        t = __hfma2(W11, u2h2(a11[k]), t);
        __half2 v = __hfma2(FV, u2h2(da[k]), u2h2(la[k]));
        feA[k] = h22u(__hmul2(t, v));
    }
    // ranks seg*48 + 8s .. +7  (16 B, aligned)
    *(uint4*)(smA + (prow * ASTR + seg * 48 + 8 * s) * 2) =
        make_uint4(feA[0], feA[1], feA[2], feA[3]);

    const unsigned* b00 = (const unsigned*)&c00.b;
    const unsigned* b01 = (const unsigned*)&c01.b;
    const unsigned* b10 = (const unsigned*)&c10.b;
    const unsigned* b11 = (const unsigned*)&c11.b;
    const unsigned* lb  = (const unsigned*)&vp.lo_b;
    const unsigned* db  = (const unsigned*)&vp.dl_b;

    unsigned feB[2];
    #pragma unroll
    for (int k = 0; k < 2; k++) {
        __half2 t = __hmul2(W00, u2h2(b00[k]));
        t = __hfma2(W01, u2h2(b01[k]), t);
        t = __hfma2(W10, u2h2(b10[k]), t);
        t = __hfma2(W11, u2h2(b11[k]), t);
        __half2 v = __hfma2(FV, u2h2(db[k]), u2h2(lb[k]));
        feB[k] = h22u(__hmul2(t, v));
    }
    // ranks seg*48 + 32 + 4s .. +3  (8 B, aligned)
    *(uint2*)(smA + (prow * ASTR + seg * 48 + 32 + 4 * s) * 2) =
        make_uint2(feB[0], feB[1]);
}

__global__ void __launch_bounds__(256, 4) sample_kernel(
    const float* __restrict__ xyz, const float* __restrict__ fvec,
    float* __restrict__ out)
{
    extern __shared__ char sm[];
    uint32_t smb = smem_u32(sm);

    int tid  = threadIdx.x;
    int lane = tid & 31;
    int warp = tid >> 5;
    int s    = lane & 3;
    int pw   = lane >> 2;
    int pp   = warp * 8 + pw;       // 0..63 within a pass
    int base = blockIdx.x * 128;

    // B fill: F as fp16 [144 k][40 halves], cols >= 27 zero
    for (int i = tid; i < 144 * BSTR / 2; i += 256) {
        int k  = i / (BSTR / 2);
        int np = i - k * (BSTR / 2);
        int n0 = 2 * np;
        float f0 = (n0     < NC) ? fvec[k * NC + n0]     : 0.0f;
        float f1 = (n0 + 1 < NC) ? fvec[k * NC + n0 + 1] : 0.0f;
        *(__half2*)(sm + OFF_B + (k * BSTR + n0) * 2) = __floats2half2_rn(f0, f1);
    }
    // xyz staging
    float* sxyz = (float*)(sm + OFF_XYZ);
    for (int i = tid; i < 384; i += 256) {
        long g = (long)base * 3 + i;
        sxyz[i] = (g < (long)NPTS * 3) ? xyz[g] : 0.5f;
    }
    __syncthreads();
    char* smA = sm + OFF_A;

    for (int pass = 0; pass < 2; pass++) {
        int prow = pass * 64 + pp;
        float x = sxyz[prow * 3 + 0];
        float y = sxyz[prow * 3 + 1];
        float z = sxyz[prow * 3 + 2];

        int ix0, ix1, iy0, iy1, iz0, iz1;
        float fx, fy, fz;
        prep_coord(x * 2.0f - 1.0f, DX, ix0, ix1, fx);
        prep_coord(y * 2.0f - 1.0f, DY, iy0, iy1, fy);
        prep_coord(z * 2.0f - 1.0f, DZ, iz0, iz1, fz);

        // corners of seg0 + seg1 up front (8 PC), vectors just-in-time
        PC c00 = ldpc(g_xyH + (u64)(ix0 * DY + iy0) * PSTR, s);
        PC c01 = ldpc(g_xyH + (u64)(ix0 * DY + iy1) * PSTR, s);
        PC c10 = ldpc(g_xyH + (u64)(ix1 * DY + iy0) * PSTR, s);
        PC c11 = ldpc(g_xyH + (u64)(ix1 * DY + iy1) * PSTR, s);

        PC n00 = ldpc(g_xzH + (u64)(ix0 * DZ + iz0) * PSTR, s);
        PC n01 = ldpc(g_xzH + (u64)(ix0 * DZ + iz1) * PSTR, s);
        PC n10 = ldpc(g_xzH + (u64)(ix1 * DZ + iz0) * PSTR, s);
        PC n11 = ldpc(g_xzH + (u64)(ix1 * DZ + iz1) * PSTR, s);

        {
            VP2 vz = ldvp(g_zvP + iz0 * VSTR, s);
            fe_seg(c00, c01, c10, c11, vz, s, fx, fy, fz, 0, prow, smA);
        }

        c00 = ldpc(g_yzH + (u64)(iy0 * DZ + iz0) * PSTR, s);
        c01 = ldpc(g_yzH + (u64)(iy0 * DZ + iz1) * PSTR, s);
        c10 = ldpc(g_yzH + (u64)(iy1 * DZ + iz0) * PSTR, s);
        c11 = ldpc(g_yzH + (u64)(iy1 * DZ + iz1) * PSTR, s);

        {
            VP2 vy = ldvp(g_yvP + iy0 * VSTR, s);
            fe_seg(n00, n01, n10, n11, vy, s, fx, fz, fy, 1, prow, smA);
        }
        {
            VP2 vx = ldvp(g_xvP + ix0 * VSTR, s);
            fe_seg(c00, c01, c10, c11, vx, s, fy, fz, fx, 2, prow, smA);
        }
    }

    __syncthreads();

    // ---- warp-level HMMA matvec ----
    float d[4][4];
    #pragma unroll
    for (int t = 0; t < 4; t++) {
        #pragma unroll
        for (int j = 0; j < 4; j++) d[t][j] = 0.0f;
    }

    uint32_t aAddr = smb + OFF_A +
                     (uint32_t)(((warp * 16 + (lane & 15)) * ASTR + (lane >> 4) * 8) * 2);
    uint32_t bAddr = smb + OFF_B +
                     (uint32_t)(((lane & 15) * BSTR + (lane >> 4) * 8) * 2);

    #pragma unroll
    for (int k = 0; k < 9; k++) {
        uint32_t a[4], b0[4], b1[4];
        ldsm_x4(aAddr + k * 32, a);
        ldsm_x4_t(bAddr + k * 16 * BSTR * 2, b0);
        ldsm_x4_t(bAddr + k * 16 * BSTR * 2 + 32, b1);
        mma16816(d[0], a, b0[0], b0[1]);
        mma16816(d[1], a, b0[2], b0[3]);
        mma16816(d[2], a, b1[0], b1[1]);
        mma16816(d[3], a, b1[2], b1[3]);
    }

    __syncthreads();

    // stage: [128][36] f32 (reuses A)
    float* stage = (float*)(sm + OFF_A);
    {
        int r0 = warp * 16 + (lane >> 2);
        int c0 = 2 * (lane & 3);
        #pragma unroll
        for (int t = 0; t < 4; t++) {
            *(float2*)(stage + r0 * 36 + 8 * t + c0)       = make_float2(d[t][0], d[t][1]);
            *(float2*)(stage + (r0 + 8) * 36 + 8 * t + c0) = make_float2(d[t][2], d[t][3]);
        }
    }
    __syncthreads();

    int lim = (NPTS - base) * NC;
    if (lim > 128 * NC) lim = 128 * NC;
    for (int i = tid; i < lim; i += 256) {
        int pt = i / NC;
        int c  = i - pt * NC;
        out[(long)base * NC + i] = stage[pt * 36 + c];
    }
}

extern "C" void kernel_launch(void* const* d_in, const int* in_sizes, int n_in,
                              void* d_out, int out_size)
{
    const float* xyz = (const float*)d_in[0];
    const float* xyp = (const float*)d_in[1];
    const float* xzp = (const float*)d_in[2];
    const float* yzp = (const float*)d_in[3];
    const float* xv  = (const float*)d_in[4];
    const float* yv  = (const float*)d_in[5];
    const float* zv  = (const float*)d_in[6];
    const float* fv  = (const float*)d_in[7];
    float* out = (float*)d_out;

    cudaFuncSetAttribute(sample_kernel,
                         cudaFuncAttributeMaxDynamicSharedMemorySize, SMEM_TOT);

    transpose_all<<<2121, 128>>>(xyp, xzp, yzp, xv, yv, zv);
    sample_kernel<<<(NPTS + 127) / 128, 256, SMEM_TOT>>>(xyz, fv, out);
}

// round 16
// speedup vs baseline: 1.1654x; 1.1654x over previous
#include <cuda_runtime.h>
#include <cuda_fp16.h>
#include <cstdint>

#define NPTS 1000000
#define DX 300
#define DY 300
#define DZ 300
#define RNK  48
#define PSTR 64     // padded halves per plane cell (128 B, line-aligned)
#define VSTR 64     // vector cell: 64 half2 = 256 B ([0..23] lo pairs, [32..55] delta pairs)
#define NC   27

// fp16 planes (cell-major, 64-half padded rows)
__device__ __align__(16) __half g_xyH[DX * DY * PSTR];
__device__ __align__(16) __half g_xzH[DX * DZ * PSTR];
__device__ __align__(16) __half g_yzH[DY * DZ * PSTR];
// fp16 vectors, lo/delta pairs: cell i, rank-pair p:
//   [i*VSTR + p]      = (v[2p][i],           v[2p+1][i])
//   [i*VSTR + 32 + p] = (v[2p][i+1]-v[2p][i], v[2p+1][i+1]-v[2p+1][i])   (i+1 clamped)
__device__ __align__(16) __half2 g_xvP[DX * VSTR];
__device__ __align__(16) __half2 g_yvP[DY * VSTR];
__device__ __align__(16) __half2 g_zvP[DZ * VSTR];

typedef unsigned long long u64;

// ---------- smem layout (dynamic, bytes) ----------
#define ASTR 152
#define BSTR 40
#define OFF_A    0
#define OFF_B    (128 * ASTR * 2)                 // 38912
#define OFF_XYZ  (OFF_B + 144 * BSTR * 2)         // 50432
#define SMEM_TOT (OFF_XYZ + 128 * 3 * 4)          // 51968

__device__ __forceinline__ uint32_t smem_u32(const void* p) {
    uint32_t a;
    asm("{ .reg .u64 t; cvta.to.shared.u64 t, %1; cvt.u32.u64 %0, t; }" : "=r"(a) : "l"(p));
    return a;
}

// ---------- ldmatrix / mma.sync ----------
__device__ __forceinline__ void ldsm_x4(uint32_t addr, uint32_t r[4]) {
    asm volatile("ldmatrix.sync.aligned.m8n8.x4.shared.b16 {%0,%1,%2,%3}, [%4];"
                 : "=r"(r[0]), "=r"(r[1]), "=r"(r[2]), "=r"(r[3]) : "r"(addr));
}
__device__ __forceinline__ void ldsm_x4_t(uint32_t addr, uint32_t r[4]) {
    asm volatile("ldmatrix.sync.aligned.m8n8.x4.trans.shared.b16 {%0,%1,%2,%3}, [%4];"
                 : "=r"(r[0]), "=r"(r[1]), "=r"(r[2]), "=r"(r[3]) : "r"(addr));
}
__device__ __forceinline__ void mma16816(float d[4], const uint32_t a[4],
                                         uint32_t b0, uint32_t b1) {
    asm volatile(
        "mma.sync.aligned.m16n8k16.row.col.f32.f16.f16.f32 "
        "{%0,%1,%2,%3}, {%4,%5,%6,%7}, {%8,%9}, {%0,%1,%2,%3};"
        : "+f"(d[0]), "+f"(d[1]), "+f"(d[2]), "+f"(d[3])
        : "r"(a[0]), "r"(a[1]), "r"(a[2]), "r"(a[3]), "r"(b0), "r"(b1));
}

// ---------- merged transpose/convert ----------
__global__ void __launch_bounds__(128) transpose_all(
    const float* __restrict__ xy, const float* __restrict__ xz,
    const float* __restrict__ yz, const float* __restrict__ xv,
    const float* __restrict__ yv, const float* __restrict__ zv)
{
    __shared__ float tile[RNK][130];
    int b = blockIdx.x;
    int t = threadIdx.x;

    if (b < 2112) {
        const float* src;
        __half* dst;
        int base;
        const int cells = DX * DY;
        if (b < 704)       { src = xy; dst = g_xyH; base = b * 128; }
        else if (b < 1408) { src = xz; dst = g_xzH; base = (b - 704) * 128; }
        else               { src = yz; dst = g_yzH; base = (b - 1408) * 128; }

        int nc = cells - base;
        if (nc > 128) nc = 128;

        #pragma unroll
        for (int r = 0; r < RNK; r++) {
            if (t < nc) tile[r][t] = src[r * cells + base + t];
        }
        __syncthreads();
        __half2* dst2 = (__half2*)dst;
        for (int i = t; i < nc * 32; i += 128) {
            int cl = i >> 5;
            int p  = i & 31;
            float lo = (2 * p     < RNK) ? tile[2 * p][cl]     : 0.0f;
            float hi = (2 * p + 1 < RNK) ? tile[2 * p + 1][cl] : 0.0f;
            dst2[(u64)(base + cl) * 32 + p] = __floats2half2_rn(lo, hi);
        }
    } else {
        int vb = b - 2112;
        int vi = vb / 3;
        int base = (vb % 3) * 128;
        const int cells = DX;
        const float* src = (vi == 0) ? xv : ((vi == 1) ? yv : zv);
        __half2* dst = (vi == 0) ? g_xvP : ((vi == 1) ? g_yvP : g_zvP);

        int nc = cells - base;
        if (nc > 128) nc = 128;
        if (nc <= 0) return;

        #pragma unroll
        for (int r = 0; r < RNK; r++) {
            if (t < nc) tile[r][t] = src[r * cells + base + t];
        }
        // boundary column: cell base+nc (clamped)
        if (t < RNK) {
            int nxt = base + nc;
            if (nxt > cells - 1) nxt = cells - 1;
            tile[t][nc] = src[t * cells + nxt];
        }
        __syncthreads();
        for (int i = t; i < nc * 24; i += 128) {    // 24 rank-pairs per cell
            int cl = i / 24;
            int p  = i - cl * 24;
            float l0 = tile[2 * p][cl],     h0 = tile[2 * p][cl + 1];
            float l1 = tile[2 * p + 1][cl], h1 = tile[2 * p + 1][cl + 1];
            dst[(base + cl) * VSTR + p]      = __floats2half2_rn(l0, l1);
            dst[(base + cl) * VSTR + 32 + p] = __floats2half2_rn(h0 - l0, h1 - l1);
        }
    }
}

__device__ __forceinline__ void prep_coord(float g, int L, int& i0, int& i1, float& f)
{
    float t  = (g + 1.0f) * 0.5f;
    float ih = t * (float)(L - 1);
    int i = (int)floorf(ih);
    i = max(0, min(i, L - 1));
    i0 = i;
    i1 = min(i + 1, L - 1);
    f = ih - (float)i;
}

// plane corner gather for lane s: 16B (ranks 8s..8s+7) + 8B (ranks 32+4s..+3)
struct PC { uint4 a; uint2 b; };
__device__ __forceinline__ PC ldpc(const __half* cell, int s)
{
    PC r;
    r.a = *(const uint4*)((const char*)cell + s * 16);
    r.b = *(const uint2*)((const char*)cell + 64 + s * 8);
    return r;
}

// vector lo/delta gather for lane s
struct VP2 { uint4 lo_a; uint2 lo_b; uint4 dl_a; uint2 dl_b; };
__device__ __forceinline__ VP2 ldvp(const __half2* cell, int s)
{
    const char* p = (const char*)cell;
    VP2 r;
    r.lo_a = *(const uint4*)(p + 16 * s);          // rank-pairs 4s..4s+3
    r.lo_b = *(const uint2*)(p + 64 + 8 * s);      // rank-pairs 16+2s..+1
    r.dl_a = *(const uint4*)(p + 128 + 16 * s);
    r.dl_b = *(const uint2*)(p + 192 + 8 * s);
    return r;
}

__device__ __forceinline__ __half2 u2h2(unsigned u) { return *(__half2*)&u; }
__device__ __forceinline__ unsigned h22u(__half2 h) { return *(unsigned*)&h; }

// one segment, pure half2 datapath: bilinear (hfma2) * vec lerp (hfma2) -> A tile
__device__ __forceinline__ void fe_seg(
    const PC& c00, const PC& c01, const PC& c10, const PC& c11,
    const VP2& vp, int s,
    float fh, float fw, float fv, int seg, int prow, char* smA)
{
    __half2 W00 = __float2half2_rn((1.0f - fh) * (1.0f - fw));
    __half2 W01 = __float2half2_rn((1.0f - fh) * fw);
    __half2 W10 = __float2half2_rn(fh * (1.0f - fw));
    __half2 W11 = __float2half2_rn(fh * fw);
    __half2 FV  = __float2half2_rn(fv);

    const unsigned* a00 = (const unsigned*)&c00.a;
    const unsigned* a01 = (const unsigned*)&c01.a;
    const unsigned* a10 = (const unsigned*)&c10.a;
    const unsigned* a11 = (const unsigned*)&c11.a;
    const unsigned* la  = (const unsigned*)&vp.lo_a;
    const unsigned* da  = (const unsigned*)&vp.dl_a;

    unsigned feA[4];
    #pragma unroll
    for (int k = 0; k < 4; k++) {
        __half2 t = __hmul2(W00, u2h2(a00[k]));
        t = __hfma2(W01, u2h2(a01[k]), t);
        t = __hfma2(W10, u2h2(a10[k]), t);
        t = __hfma2(W11, u2h2(a11[k]), t);
        __half2 v = __hfma2(FV, u2h2(da[k]), u2h2(la[k]));
        feA[k] = h22u(__hmul2(t, v));
    }
    // ranks seg*48 + 8s .. +7  (16 B, aligned)
    *(uint4*)(smA + (prow * ASTR + seg * 48 + 8 * s) * 2) =
        make_uint4(feA[0], feA[1], feA[2], feA[3]);

    const unsigned* b00 = (const unsigned*)&c00.b;
    const unsigned* b01 = (const unsigned*)&c01.b;
    const unsigned* b10 = (const unsigned*)&c10.b;
    const unsigned* b11 = (const unsigned*)&c11.b;
    const unsigned* lb  = (const unsigned*)&vp.lo_b;
    const unsigned* db  = (const unsigned*)&vp.dl_b;

    unsigned feB[2];
    #pragma unroll
    for (int k = 0; k < 2; k++) {
        __half2 t = __hmul2(W00, u2h2(b00[k]));
        t = __hfma2(W01, u2h2(b01[k]), t);
        t = __hfma2(W10, u2h2(b10[k]), t);
        t = __hfma2(W11, u2h2(b11[k]), t);
        __half2 v = __hfma2(FV, u2h2(db[k]), u2h2(lb[k]));
        feB[k] = h22u(__hmul2(t, v));
    }
    // ranks seg*48 + 32 + 4s .. +3  (8 B, aligned)
    *(uint2*)(smA + (prow * ASTR + seg * 48 + 32 + 4 * s) * 2) =
        make_uint2(feB[0], feB[1]);
}

__global__ void __launch_bounds__(256, 3) sample_kernel(
    const float* __restrict__ xyz, const float* __restrict__ fvec,
    float* __restrict__ out)
{
    extern __shared__ char sm[];
    uint32_t smb = smem_u32(sm);

    int tid  = threadIdx.x;
    int lane = tid & 31;
    int warp = tid >> 5;
    int s    = lane & 3;
    int pw   = lane >> 2;
    int pp   = warp * 8 + pw;       // 0..63 within a pass
    int base = blockIdx.x * 128;

    // B fill: F as fp16 [144 k][40 halves], cols >= 27 zero
    for (int i = tid; i < 144 * BSTR / 2; i += 256) {
        int k  = i / (BSTR / 2);
        int np = i - k * (BSTR / 2);
        int n0 = 2 * np;
        float f0 = (n0     < NC) ? fvec[k * NC + n0]     : 0.0f;
        float f1 = (n0 + 1 < NC) ? fvec[k * NC + n0 + 1] : 0.0f;
        *(__half2*)(sm + OFF_B + (k * BSTR + n0) * 2) = __floats2half2_rn(f0, f1);
    }
    // xyz staging
    float* sxyz = (float*)(sm + OFF_XYZ);
    for (int i = tid; i < 384; i += 256) {
        long g = (long)base * 3 + i;
        sxyz[i] = (g < (long)NPTS * 3) ? xyz[g] : 0.5f;
    }
    __syncthreads();
    char* smA = sm + OFF_A;

    for (int pass = 0; pass < 2; pass++) {
        int prow = pass * 64 + pp;
        float x = sxyz[prow * 3 + 0];
        float y = sxyz[prow * 3 + 1];
        float z = sxyz[prow * 3 + 2];

        int ix0, ix1, iy0, iy1, iz0, iz1;
        float fx, fy, fz;
        prep_coord(x * 2.0f - 1.0f, DX, ix0, ix1, fx);
        prep_coord(y * 2.0f - 1.0f, DY, iy0, iy1, fy);
        prep_coord(z * 2.0f - 1.0f, DZ, iz0, iz1, fz);

        // corners of seg0 + seg1 up front (8 PC), vectors just-in-time
        PC c00 = ldpc(g_xyH + (u64)(ix0 * DY + iy0) * PSTR, s);
        PC c01 = ldpc(g_xyH + (u64)(ix0 * DY + iy1) * PSTR, s);
        PC c10 = ldpc(g_xyH + (u64)(ix1 * DY + iy0) * PSTR, s);
        PC c11 = ldpc(g_xyH + (u64)(ix1 * DY + iy1) * PSTR, s);

        PC n00 = ldpc(g_xzH + (u64)(ix0 * DZ + iz0) * PSTR, s);
        PC n01 = ldpc(g_xzH + (u64)(ix0 * DZ + iz1) * PSTR, s);
        PC n10 = ldpc(g_xzH + (u64)(ix1 * DZ + iz0) * PSTR, s);
        PC n11 = ldpc(g_xzH + (u64)(ix1 * DZ + iz1) * PSTR, s);

        {
            VP2 vz = ldvp(g_zvP + iz0 * VSTR, s);
            fe_seg(c00, c01, c10, c11, vz, s, fx, fy, fz, 0, prow, smA);
        }

        c00 = ldpc(g_yzH + (u64)(iy0 * DZ + iz0) * PSTR, s);
        c01 = ldpc(g_yzH + (u64)(iy0 * DZ + iz1) * PSTR, s);
        c10 = ldpc(g_yzH + (u64)(iy1 * DZ + iz0) * PSTR, s);
        c11 = ldpc(g_yzH + (u64)(iy1 * DZ + iz1) * PSTR, s);

        {
            VP2 vy = ldvp(g_yvP + iy0 * VSTR, s);
            fe_seg(n00, n01, n10, n11, vy, s, fx, fz, fy, 1, prow, smA);
        }
        {
            VP2 vx = ldvp(g_xvP + ix0 * VSTR, s);
            fe_seg(c00, c01, c10, c11, vx, s, fy, fz, fx, 2, prow, smA);
        }
    }

    __syncthreads();

    // ---- warp-level HMMA matvec ----
    float d[4][4];
    #pragma unroll
    for (int t = 0; t < 4; t++) {
        #pragma unroll
        for (int j = 0; j < 4; j++) d[t][j] = 0.0f;
    }

    uint32_t aAddr = smb + OFF_A +
                     (uint32_t)(((warp * 16 + (lane & 15)) * ASTR + (lane >> 4) * 8) * 2);
    uint32_t bAddr = smb + OFF_B +
                     (uint32_t)(((lane & 15) * BSTR + (lane >> 4) * 8) * 2);

    #pragma unroll
    for (int k = 0; k < 9; k++) {
        uint32_t a[4], b0[4], b1[4];
        ldsm_x4(aAddr + k * 32, a);
        ldsm_x4_t(bAddr + k * 16 * BSTR * 2, b0);
        ldsm_x4_t(bAddr + k * 16 * BSTR * 2 + 32, b1);
        mma16816(d[0], a, b0[0], b0[1]);
        mma16816(d[1], a, b0[2], b0[3]);
        mma16816(d[2], a, b1[0], b1[1]);
        mma16816(d[3], a, b1[2], b1[3]);
    }

    __syncthreads();

    // stage: [128][36] f32 (reuses A)
    float* stage = (float*)(sm + OFF_A);
    {
        int r0 = warp * 16 + (lane >> 2);
        int c0 = 2 * (lane & 3);
        #pragma unroll
        for (int t = 0; t < 4; t++) {
            *(float2*)(stage + r0 * 36 + 8 * t + c0)       = make_float2(d[t][0], d[t][1]);
            *(float2*)(stage + (r0 + 8) * 36 + 8 * t + c0) = make_float2(d[t][2], d[t][3]);
        }
    }
    __syncthreads();

    int lim = (NPTS - base) * NC;
    if (lim > 128 * NC) lim = 128 * NC;
    for (int i = tid; i < lim; i += 256) {
        int pt = i / NC;
        int c  = i - pt * NC;
        out[(long)base * NC + i] = stage[pt * 36 + c];
    }
}

extern "C" void kernel_launch(void* const* d_in, const int* in_sizes, int n_in,
                              void* d_out, int out_size)
{
    const float* xyz = (const float*)d_in[0];
    const float* xyp = (const float*)d_in[1];
    const float* xzp = (const float*)d_in[2];
    const float* yzp = (const float*)d_in[3];
    const float* xv  = (const float*)d_in[4];
    const float* yv  = (const float*)d_in[5];
    const float* zv  = (const float*)d_in[6];
    const float* fv  = (const float*)d_in[7];
    float* out = (float*)d_out;

    cudaFuncSetAttribute(sample_kernel,
                         cudaFuncAttributeMaxDynamicSharedMemorySize, SMEM_TOT);

    transpose_all<<<2121, 128>>>(xyp, xzp, yzp, xv, yv, zv);
    sample_kernel<<<(NPTS + 127) / 128, 256, SMEM_TOT>>>(xyz, fv, out);
}

// round 17
// speedup vs baseline: 1.3485x; 1.1571x over previous
#include <cuda_runtime.h>
#include <cuda_fp16.h>
#include <cstdint>

#define NPTS 1000000
#define DX 300
#define DY 300
#define DZ 300
#define RNK  48
#define PSTR 64     // padded halves per plane cell (128 B, line-aligned; halves 48..63 = 0)
#define VSTR 64     // vector cell: 64 half2 = 256 B ([0..23] lo pairs, [32..55] delta pairs)
#define NC   27

// fp16 planes (cell-major, 64-half padded rows)
__device__ __align__(16) __half g_xyH[DX * DY * PSTR];
__device__ __align__(16) __half g_xzH[DX * DZ * PSTR];
__device__ __align__(16) __half g_yzH[DY * DZ * PSTR];
// fp16 vectors, lo/delta pairs (see transpose_all)
__device__ __align__(16) __half2 g_xvP[DX * VSTR];
__device__ __align__(16) __half2 g_yvP[DY * VSTR];
__device__ __align__(16) __half2 g_zvP[DZ * VSTR];

typedef unsigned long long u64;

// ---------- smem layout (dynamic, bytes) ----------
#define ASTR 152
#define BSTR 40
#define OFF_A    0
#define OFF_B    (128 * ASTR * 2)                 // 38912
#define OFF_XYZ  (OFF_B + 144 * BSTR * 2)         // 50432
#define SMEM_TOT (OFF_XYZ + 128 * 3 * 4)          // 51968

__device__ __forceinline__ uint32_t smem_u32(const void* p) {
    uint32_t a;
    asm("{ .reg .u64 t; cvta.to.shared.u64 t, %1; cvt.u32.u64 %0, t; }" : "=r"(a) : "l"(p));
    return a;
}

// ---------- ldmatrix / mma.sync ----------
__device__ __forceinline__ void ldsm_x4(uint32_t addr, uint32_t r[4]) {
    asm volatile("ldmatrix.sync.aligned.m8n8.x4.shared.b16 {%0,%1,%2,%3}, [%4];"
                 : "=r"(r[0]), "=r"(r[1]), "=r"(r[2]), "=r"(r[3]) : "r"(addr));
}
__device__ __forceinline__ void ldsm_x4_t(uint32_t addr, uint32_t r[4]) {
    asm volatile("ldmatrix.sync.aligned.m8n8.x4.trans.shared.b16 {%0,%1,%2,%3}, [%4];"
                 : "=r"(r[0]), "=r"(r[1]), "=r"(r[2]), "=r"(r[3]) : "r"(addr));
}
__device__ __forceinline__ void mma16816(float d[4], const uint32_t a[4],
                                         uint32_t b0, uint32_t b1) {
    asm volatile(
        "mma.sync.aligned.m16n8k16.row.col.f32.f16.f16.f32 "
        "{%0,%1,%2,%3}, {%4,%5,%6,%7}, {%8,%9}, {%0,%1,%2,%3};"
        : "+f"(d[0]), "+f"(d[1]), "+f"(d[2]), "+f"(d[3])
        : "r"(a[0]), "r"(a[1]), "r"(a[2]), "r"(a[3]), "r"(b0), "r"(b1));
}

// ---------- merged transpose/convert (unchanged) ----------
__global__ void __launch_bounds__(128) transpose_all(
    const float* __restrict__ xy, const float* __restrict__ xz,
    const float* __restrict__ yz, const float* __restrict__ xv,
    const float* __restrict__ yv, const float* __restrict__ zv)
{
    __shared__ float tile[RNK][130];
    int b = blockIdx.x;
    int t = threadIdx.x;

    if (b < 2112) {
        const float* src;
        __half* dst;
        int base;
        const int cells = DX * DY;
        if (b < 704)       { src = xy; dst = g_xyH; base = b * 128; }
        else if (b < 1408) { src = xz; dst = g_xzH; base = (b - 704) * 128; }
        else               { src = yz; dst = g_yzH; base = (b - 1408) * 128; }

        int nc = cells - base;
        if (nc > 128) nc = 128;

        #pragma unroll
        for (int r = 0; r < RNK; r++) {
            if (t < nc) tile[r][t] = src[r * cells + base + t];
        }
        __syncthreads();
        __half2* dst2 = (__half2*)dst;
        for (int i = t; i < nc * 32; i += 128) {
            int cl = i >> 5;
            int p  = i & 31;
            float lo = (2 * p     < RNK) ? tile[2 * p][cl]     : 0.0f;
            float hi = (2 * p + 1 < RNK) ? tile[2 * p + 1][cl] : 0.0f;
            dst2[(u64)(base + cl) * 32 + p] = __floats2half2_rn(lo, hi);
        }
    } else {
        int vb = b - 2112;
        int vi = vb / 3;
        int base = (vb % 3) * 128;
        const int cells = DX;
        const float* src = (vi == 0) ? xv : ((vi == 1) ? yv : zv);
        __half2* dst = (vi == 0) ? g_xvP : ((vi == 1) ? g_yvP : g_zvP);

        int nc = cells - base;
        if (nc > 128) nc = 128;
        if (nc <= 0) return;

        #pragma unroll
        for (int r = 0; r < RNK; r++) {
            if (t < nc) tile[r][t] = src[r * cells + base + t];
        }
        if (t < RNK) {
            int nxt = base + nc;
            if (nxt > cells - 1) nxt = cells - 1;
            tile[t][nc] = src[t * cells + nxt];
        }
        __syncthreads();
        // zero pads so 8-lane loads of slots 24..31 / 56..63 are safe
        for (int i = t; i < nc * 64; i += 128) {
            int cl = i >> 6;
            int p  = i & 63;
            __half2 v = __floats2half2_rn(0.0f, 0.0f);
            if (p < 24) {
                v = __floats2half2_rn(tile[2 * p][cl], tile[2 * p + 1][cl]);
            } else if (p >= 32 && p < 56) {
                int q = p - 32;
                v = __floats2half2_rn(tile[2 * q][cl + 1] - tile[2 * q][cl],
                                      tile[2 * q + 1][cl + 1] - tile[2 * q + 1][cl]);
            }
            dst[(base + cl) * VSTR + p] = v;
        }
    }
}

__device__ __forceinline__ void prep_coord(float g, int L, int& i0, int& i1, float& f)
{
    float t  = (g + 1.0f) * 0.5f;
    float ih = t * (float)(L - 1);
    int i = (int)floorf(ih);
    i = max(0, min(i, L - 1));
    i0 = i;
    i1 = min(i + 1, L - 1);
    f = ih - (float)i;
}

__device__ __forceinline__ __half2 u2h2(unsigned u) { return *(__half2*)&u; }
__device__ __forceinline__ unsigned h22u(__half2 h) { return *(unsigned*)&h; }

// 16 B slice of a 128 B-aligned cell line, lane-selected
__device__ __forceinline__ uint4 ld16(const void* cell, int s)
{
    return *(const uint4*)((const char*)cell + s * 16);
}

// one segment, 8-lane datapath: lane s owns ranks 8s..8s+7 (s<6; s=6,7 pad).
// bilinear (hfma2) * vec lerp (hfma2) -> one STS.128 into the A tile.
__device__ __forceinline__ void fe_seg8(
    uint4 c00, uint4 c01, uint4 c10, uint4 c11,
    uint4 lo, uint4 dl,
    float fh, float fw, float fv, int seg, int prow, int s, char* smA)
{
    __half2 W00 = __float2half2_rn((1.0f - fh) * (1.0f - fw));
    __half2 W01 = __float2half2_rn((1.0f - fh) * fw);
    __half2 W10 = __float2half2_rn(fh * (1.0f - fw));
    __half2 W11 = __float2half2_rn(fh * fw);
    __half2 FV  = __float2half2_rn(fv);

    const unsigned* a00 = (const unsigned*)&c00;
    const unsigned* a01 = (const unsigned*)&c01;
    const unsigned* a10 = (const unsigned*)&c10;
    const unsigned* a11 = (const unsigned*)&c11;
    const unsigned* la  = (const unsigned*)&lo;
    const unsigned* da  = (const unsigned*)&dl;

    unsigned fe[4];
    #pragma unroll
    for (int k = 0; k < 4; k++) {
        __half2 t = __hmul2(W00, u2h2(a00[k]));
        t = __hfma2(W01, u2h2(a01[k]), t);
        t = __hfma2(W10, u2h2(a10[k]), t);
        t = __hfma2(W11, u2h2(a11[k]), t);
        __half2 v = __hfma2(FV, u2h2(da[k]), u2h2(la[k]));
        fe[k] = h22u(__hmul2(t, v));
    }
    if (s < 6) {
        *(uint4*)(smA + (prow * ASTR + seg * 48 + 8 * s) * 2) =
            make_uint4(fe[0], fe[1], fe[2], fe[3]);
    }
}

__global__ void __launch_bounds__(256, 3) sample_kernel(
    const float* __restrict__ xyz, const float* __restrict__ fvec,
    float* __restrict__ out)
{
    extern __shared__ char sm[];
    uint32_t smb = smem_u32(sm);

    int tid  = threadIdx.x;
    int lane = tid & 31;
    int warp = tid >> 5;
    int s    = lane & 7;        // 8 lanes per point
    int pw   = lane >> 3;       // point within warp (0..3)
    int base = blockIdx.x * 128;

    // B fill: F as fp16 [144 k][40 halves], cols >= 27 zero
    for (int i = tid; i < 144 * BSTR / 2; i += 256) {
        int k  = i / (BSTR / 2);
        int np = i - k * (BSTR / 2);
        int n0 = 2 * np;
        float f0 = (n0     < NC) ? fvec[k * NC + n0]     : 0.0f;
        float f1 = (n0 + 1 < NC) ? fvec[k * NC + n0 + 1] : 0.0f;
        *(__half2*)(sm + OFF_B + (k * BSTR + n0) * 2) = __floats2half2_rn(f0, f1);
    }
    // xyz staging
    float* sxyz = (float*)(sm + OFF_XYZ);
    for (int i = tid; i < 384; i += 256) {
        long g = (long)base * 3 + i;
        sxyz[i] = (g < (long)NPTS * 3) ? xyz[g] : 0.5f;
    }
    __syncthreads();
    char* smA = sm + OFF_A;

    #pragma unroll 1
    for (int pass = 0; pass < 4; pass++) {
        int prow = pass * 32 + warp * 4 + pw;
        float x = sxyz[prow * 3 + 0];
        float y = sxyz[prow * 3 + 1];
        float z = sxyz[prow * 3 + 2];

        int ix0, ix1, iy0, iy1, iz0, iz1;
        float fx, fy, fz;
        prep_coord(x * 2.0f - 1.0f, DX, ix0, ix1, fx);
        prep_coord(y * 2.0f - 1.0f, DY, iy0, iy1, fy);
        prep_coord(z * 2.0f - 1.0f, DZ, iz0, iz1, fz);

        // prefetch ALL 12 plane corners (one LDG.128 each; MLP = 12)
        uint4 p00 = ld16(g_xyH + (u64)(ix0 * DY + iy0) * PSTR, s);
        uint4 p01 = ld16(g_xyH + (u64)(ix0 * DY + iy1) * PSTR, s);
        uint4 p10 = ld16(g_xyH + (u64)(ix1 * DY + iy0) * PSTR, s);
        uint4 p11 = ld16(g_xyH + (u64)(ix1 * DY + iy1) * PSTR, s);

        uint4 q00 = ld16(g_xzH + (u64)(ix0 * DZ + iz0) * PSTR, s);
        uint4 q01 = ld16(g_xzH + (u64)(ix0 * DZ + iz1) * PSTR, s);
        uint4 q10 = ld16(g_xzH + (u64)(ix1 * DZ + iz0) * PSTR, s);
        uint4 q11 = ld16(g_xzH + (u64)(ix1 * DZ + iz1) * PSTR, s);

        uint4 r00 = ld16(g_yzH + (u64)(iy0 * DZ + iz0) * PSTR, s);
        uint4 r01 = ld16(g_yzH + (u64)(iy0 * DZ + iz1) * PSTR, s);
        uint4 r10 = ld16(g_yzH + (u64)(iy1 * DZ + iz0) * PSTR, s);
        uint4 r11 = ld16(g_yzH + (u64)(iy1 * DZ + iz1) * PSTR, s);

        {
            uint4 lo = ld16(g_zvP + iz0 * VSTR, s);
            uint4 dl = ld16((const char*)(g_zvP + iz0 * VSTR) + 128, s);
            fe_seg8(p00, p01, p10, p11, lo, dl, fx, fy, fz, 0, prow, s, smA);
        }
        {
            uint4 lo = ld16(g_yvP + iy0 * VSTR, s);
            uint4 dl = ld16((const char*)(g_yvP + iy0 * VSTR) + 128, s);
            fe_seg8(q00, q01, q10, q11, lo, dl, fx, fz, fy, 1, prow, s, smA);
        }
        {
            uint4 lo = ld16(g_xvP + ix0 * VSTR, s);
            uint4 dl = ld16((const char*)(g_xvP + ix0 * VSTR) + 128, s);
            fe_seg8(r00, r01, r10, r11, lo, dl, fy, fz, fx, 2, prow, s, smA);
        }
    }

    __syncthreads();

    // ---- warp-level HMMA matvec (unchanged) ----
    float d[4][4];
    #pragma unroll
    for (int t = 0; t < 4; t++) {
        #pragma unroll
        for (int j = 0; j < 4; j++) d[t][j] = 0.0f;
    }

    uint32_t aAddr = smb + OFF_A +
                     (uint32_t)(((warp * 16 + (lane & 15)) * ASTR + (lane >> 4) * 8) * 2);
    uint32_t bAddr = smb + OFF_B +
                     (uint32_t)(((lane & 15) * BSTR + (lane >> 4) * 8) * 2);

    #pragma unroll
    for (int k = 0; k < 9; k++) {
        uint32_t a[4], b0[4], b1[4];
        ldsm_x4(aAddr + k * 32, a);
        ldsm_x4_t(bAddr + k * 16 * BSTR * 2, b0);
        ldsm_x4_t(bAddr + k * 16 * BSTR * 2 + 32, b1);
        mma16816(d[0], a, b0[0], b0[1]);
        mma16816(d[1], a, b0[2], b0[3]);
        mma16816(d[2], a, b1[0], b1[1]);
        mma16816(d[3], a, b1[2], b1[3]);
    }

    __syncthreads();

    // stage: [128][36] f32 (reuses A)
    float* stage = (float*)(sm + OFF_A);
    {
        int r0 = warp * 16 + (lane >> 2);
        int c0 = 2 * (lane & 3);
        #pragma unroll
        for (int t = 0; t < 4; t++) {
            *(float2*)(stage + r0 * 36 + 8 * t + c0)       = make_float2(d[t][0], d[t][1]);
            *(float2*)(stage + (r0 + 8) * 36 + 8 * t + c0) = make_float2(d[t][2], d[t][3]);
        }
    }
    __syncthreads();

    int lim = (NPTS - base) * NC;
    if (lim > 128 * NC) lim = 128 * NC;
    for (int i = tid; i < lim; i += 256) {
        int pt = i / NC;
        int c  = i - pt * NC;
        out[(long)base * NC + i] = stage[pt * 36 + c];
    }
}

extern "C" void kernel_launch(void* const* d_in, const int* in_sizes, int n_in,
                              void* d_out, int out_size)
{
    const float* xyz = (const float*)d_in[0];
    const float* xyp = (const float*)d_in[1];
    const float* xzp = (const float*)d_in[2];
    const float* yzp = (const float*)d_in[3];
    const float* xv  = (const float*)d_in[4];
    const float* yv  = (const float*)d_in[5];
    const float* zv  = (const float*)d_in[6];
    const float* fv  = (const float*)d_in[7];
    float* out = (float*)d_out;

    cudaFuncSetAttribute(sample_kernel,
                         cudaFuncAttributeMaxDynamicSharedMemorySize, SMEM_TOT);

    transpose_all<<<2121, 128>>>(xyp, xzp, yzp, xv, yv, zv);
    sample_kernel<<<(NPTS + 127) / 128, 256, SMEM_TOT>>>(xyz, fv, out);
}